// round 1
// baseline (speedup 1.0000x reference)
#include <cuda_runtime.h>
#include <math.h>

// ---------------- problem constants ----------------
#define Nn      129
#define Fdim    262144
#define Ee      16384
#define CHUNKS  16
#define CHF     (Fdim / CHUNKS)        // 16384 floats per chunk
#define DOTBLK  (Nn * CHUNKS)          // 2064 dot blocks
#define DEGBLK  32                     // deg blocks appended to K1
#define PADS    256                    // float stride (1024B) so each accumulator hits its own L2 slice

// ---------------- device scratch (static, allowed) ----------------
__device__ float g_partial[Nn * CHUNKS];     // per-(row,chunk) dot partials
__device__ float g_deg [3 * Nn * PADS];      // padded atomic accumulators
__device__ float g_h1  [3 * Nn * PADS];
__device__ float g_h2  [3 * Nn * PADS];
__device__ float g_xw  [Nn];                 // x @ W1
__device__ float g_dinv[3 * Nn];             // deg^-1/2 per channel
__device__ float g_h1f [3 * Nn];             // finalized layer-1 output

// ---------------- K0: zero the accumulator slots ----------------
__global__ void k0_zero() {
    int i = blockIdx.x * blockDim.x + threadIdx.x;
    for (; i < 3 * Nn; i += gridDim.x * blockDim.x) {
        g_deg[i * PADS] = 0.f;
        g_h1 [i * PADS] = 0.f;
        g_h2 [i * PADS] = 0.f;
    }
}

// ---------------- K1: fused  xw partial dots  +  degree scatter ----------------
__global__ void k1_dot_deg(const float* __restrict__ x,
                           const float* __restrict__ w,
                           const int*   __restrict__ ei,
                           const float* __restrict__ ea) {
    __shared__ float sred[8];
    int b = blockIdx.x;
    int t = threadIdx.x;
    if (b < DOTBLK) {
        int r = b / CHUNKS, c = b % CHUNKS;
        const float4* xp = (const float4*)x + ((size_t)r * Fdim + (size_t)c * CHF) / 4;
        const float4* wp = (const float4*)w + ((size_t)c * CHF) / 4;
        float acc = 0.f;
#pragma unroll
        for (int i = 0; i < CHF / 4 / 256; i++) {         // 16 float4 pairs per thread
            float4 a  = xp[t + i * 256];
            float4 bb = wp[t + i * 256];
            acc = fmaf(a.x, bb.x, acc);
            acc = fmaf(a.y, bb.y, acc);
            acc = fmaf(a.z, bb.z, acc);
            acc = fmaf(a.w, bb.w, acc);
        }
#pragma unroll
        for (int o = 16; o > 0; o >>= 1) acc += __shfl_down_sync(0xffffffffu, acc, o);
        if ((t & 31) == 0) sred[t >> 5] = acc;
        __syncthreads();
        if (t == 0) {
            float s = 0.f;
#pragma unroll
            for (int i = 0; i < 8; i++) s += sred[i];
            g_partial[r * CHUNKS + c] = s;
        }
    } else {
        // degree scatter: deg[ch][col[e]] += ea[e][ch]
        const int* col = ei + Ee;
        int base = (b - DOTBLK) * 256 + t;                // 0..8191
        for (int e = base; e < Ee; e += DEGBLK * 256) {
            int cc = col[e];
#pragma unroll
            for (int ch = 0; ch < 3; ch++)
                atomicAdd(&g_deg[(ch * Nn + cc) * PADS], ea[e * 3 + ch]);
        }
    }
}

// ---------------- K2: reduce dot partials + dinv ----------------
__global__ void k2_xw_dinv() {
    int t = threadIdx.x;
    for (int n = t; n < Nn; n += 256) {
        float s = 0.f;
#pragma unroll
        for (int c = 0; c < CHUNKS; c++) s += g_partial[n * CHUNKS + c];
        g_xw[n] = s;
    }
    for (int i = t; i < 3 * Nn; i += 256) {
        float deg = g_deg[i * PADS] + 1.0f;               // +1 self loop
        g_dinv[i] = (deg > 0.f) ? rsqrtf(deg) : 0.f;
    }
}

// ---------------- K3: layer-1 edge aggregation ----------------
__global__ void k3_agg1(const int* __restrict__ ei, const float* __restrict__ ea) {
    int e = blockIdx.x * blockDim.x + threadIdx.x;
    if (e >= Ee) return;
    int r = ei[e], c = ei[Ee + e];
#pragma unroll
    for (int ch = 0; ch < 3; ch++) {
        float ew  = ea[e * 3 + ch];
        float nrm = g_dinv[ch * Nn + r] * ew * g_dinv[ch * Nn + c];
        atomicAdd(&g_h1[(ch * Nn + c) * PADS], nrm * g_xw[r]);
    }
}

// ---------------- K4: finalize h1 (self loop + bias) ----------------
__global__ void k4_fin1(const float* __restrict__ gcn1_b) {
    float b1 = gcn1_b[0];
    for (int i = threadIdx.x; i < 3 * Nn; i += 256) {
        int n = i % Nn;
        float di = g_dinv[i];
        g_h1f[i] = g_h1[i * PADS] + di * di * g_xw[n] + b1;
    }
}

// ---------------- K5: layer-2 edge aggregation ----------------
__global__ void k5_agg2(const int* __restrict__ ei, const float* __restrict__ ea,
                        const float* __restrict__ gcn2_W) {
    int e = blockIdx.x * blockDim.x + threadIdx.x;
    if (e >= Ee) return;
    float W2 = gcn2_W[0];
    int r = ei[e], c = ei[Ee + e];
#pragma unroll
    for (int ch = 0; ch < 3; ch++) {
        float ew  = ea[e * 3 + ch];
        float nrm = g_dinv[ch * Nn + r] * ew * g_dinv[ch * Nn + c];
        atomicAdd(&g_h2[(ch * Nn + c) * PADS], nrm * g_h1f[ch * Nn + r] * W2);
    }
}

// ---------------- K6: tail — finalize h2, sort, convs, FCs ----------------
__device__ __forceinline__ float eluf(float a) { return a > 0.f ? a : expm1f(a); }
__device__ __forceinline__ float max3(const float* p) {
    return fmaxf(p[0], fmaxf(p[1], p[2]));
}

__global__ void k6_tail(const float* __restrict__ gcn2_W, const float* __restrict__ gcn2_b,
                        const float* __restrict__ c1w, const float* __restrict__ c1b,
                        const float* __restrict__ c2w, const float* __restrict__ c2b,
                        const float* __restrict__ f1W, const float* __restrict__ f1b,
                        const float* __restrict__ f2W, const float* __restrict__ f2b,
                        const float* __restrict__ f3W, const float* __restrict__ f3b,
                        float* __restrict__ out) {
    __shared__ float s_h1a[3 * Nn], s_h2a[3 * Nn];
    __shared__ float z0[Nn], z1[Nn];
    __shared__ float c1[3 * 127], p1[3 * 125], c2[123];
    __shared__ float s_allx[3 * 121];
    __shared__ float f1[32], f2[6];

    int t = threadIdx.x;
    float W2 = gcn2_W[0], b2 = gcn2_b[0];

    for (int i = t; i < 3 * Nn; i += 256) {
        float di = g_dinv[i];
        float h1 = g_h1f[i];
        s_h1a[i] = h1;
        s_h2a[i] = g_h2[i * PADS] + di * di * h1 * W2 + b2;
    }
    __syncthreads();

    for (int ch = 0; ch < 3; ch++) {
        // ---- SortPool: stable descending sort by h2 (O(N^2) rank) ----
        if (t < Nn) {
            float key = s_h2a[ch * Nn + t];
            float v1  = s_h1a[ch * Nn + t];
            int rank = 0;
            for (int m = 0; m < Nn; m++) {
                float km = s_h2a[ch * Nn + m];
                rank += (km > key) || (km == key && m < t);
            }
            z0[rank] = v1;
            z1[rank] = key;
        }
        __syncthreads();

        // ---- conv1: 2->3 channels, k=3, VALID -> length 127 ----
        if (t < 127) {
#pragma unroll
            for (int o = 0; o < 3; o++) {
                float a = c1b[o];
#pragma unroll
                for (int k = 0; k < 3; k++) {
                    a = fmaf(c1w[o * 6 + 0 * 3 + k], z0[t + k], a);
                    a = fmaf(c1w[o * 6 + 1 * 3 + k], z1[t + k], a);
                }
                c1[o * 127 + t] = a;
            }
        }
        __syncthreads();

        // ---- maxpool3 -> 125 ----
        if (t < 125) {
#pragma unroll
            for (int o = 0; o < 3; o++) p1[o * 125 + t] = max3(&c1[o * 127 + t]);
        }
        __syncthreads();

        // ---- conv2: 3->1, k=3 -> 123 ----
        if (t < 123) {
            float a = c2b[0];
#pragma unroll
            for (int in = 0; in < 3; in++)
#pragma unroll
                for (int k = 0; k < 3; k++)
                    a = fmaf(c2w[in * 3 + k], p1[in * 125 + t + k], a);
            c2[t] = a;
        }
        __syncthreads();

        // ---- maxpool3 -> 121 ----
        if (t < 121) s_allx[ch * 121 + t] = max3(&c2[t]);
        __syncthreads();
    }

    // ---- fc1: 363 -> 32, elu ----
    if (t < 32) {
        float a = f1b[t];
        for (int i = 0; i < 363; i++) a = fmaf(s_allx[i], f1W[i * 32 + t], a);
        f1[t] = eluf(a);
    }
    __syncthreads();
    // ---- fc2: 32 -> 6, elu ----
    if (t < 6) {
        float a = f2b[t];
#pragma unroll
        for (int i = 0; i < 32; i++) a = fmaf(f1[i], f2W[i * 6 + t], a);
        f2[t] = eluf(a);
    }
    __syncthreads();
    // ---- fc3: 6 -> 2 ----
    if (t < 2) {
        float a = f3b[t];
#pragma unroll
        for (int i = 0; i < 6; i++) a = fmaf(f2[i], f3W[i * 2 + t], a);
        out[t] = a;
    }
}

// ---------------- launch ----------------
extern "C" void kernel_launch(void* const* d_in, const int* in_sizes, int n_in,
                              void* d_out, int out_size) {
    const float* x    = (const float*)d_in[0];
    const int*   ei   = (const int*)  d_in[1];
    const float* ea   = (const float*)d_in[2];
    const float* g1W  = (const float*)d_in[3];
    const float* g1b  = (const float*)d_in[4];
    const float* g2W  = (const float*)d_in[5];
    const float* g2b  = (const float*)d_in[6];
    const float* c1w  = (const float*)d_in[7];
    const float* c1b  = (const float*)d_in[8];
    const float* c2w  = (const float*)d_in[9];
    const float* c2b  = (const float*)d_in[10];
    const float* f1W  = (const float*)d_in[11];
    const float* f1b  = (const float*)d_in[12];
    const float* f2W  = (const float*)d_in[13];
    const float* f2b  = (const float*)d_in[14];
    const float* f3W  = (const float*)d_in[15];
    const float* f3b  = (const float*)d_in[16];
    float* out = (float*)d_out;

    k0_zero   <<<4, 256>>>();
    k1_dot_deg<<<DOTBLK + DEGBLK, 256>>>(x, g1W, ei, ea);
    k2_xw_dinv<<<1, 256>>>();
    k3_agg1   <<<Ee / 256, 256>>>(ei, ea);
    k4_fin1   <<<1, 256>>>(g1b);
    k5_agg2   <<<Ee / 256, 256>>>(ei, ea, g2W);
    k6_tail   <<<1, 256>>>(g2W, g2b, c1w, c1b, c2w, c2b,
                           f1W, f1b, f2W, f2b, f3W, f3b, out);
}

// round 2
// speedup vs baseline: 1.1917x; 1.1917x over previous
#include <cuda_runtime.h>
#include <math.h>

// ---------------- problem constants ----------------
#define Nn      129
#define Fdim    262144
#define Ee      16384
#define CHUNKS  16
#define CHF     (Fdim / CHUNKS)        // 16384 floats per chunk
#define TILES   (Nn * CHUNKS)          // 2064 dot tiles
#define GRID    148                    // <= SM count, all blocks resident
#define NTHR    1024
#define PADS    256                    // 1024B stride -> distinct L2 slices for atomics
#define XPAD    32                     // 128B stride for xw accumulators

// ---------------- device scratch (zero-initialized at load; each run re-zeroes at end) ----
__device__ float    g_xwa[Nn * XPAD];
__device__ float    g_deg[3 * Nn * PADS];
__device__ float    g_h1 [3 * Nn * PADS];
__device__ float    g_h2 [3 * Nn * PADS];
__device__ unsigned g_bar[4];

// ---------------- grid barrier: monotonic counter, replay-safe, no reset ----------------
__device__ __forceinline__ void gridbar(int k) {
    __syncthreads();
    __threadfence();
    if (threadIdx.x == 0) {
        unsigned v = atomicAdd(&g_bar[k], 1u);
        unsigned target = (v / GRID) * GRID + GRID;
        while (atomicAdd(&g_bar[k], 0u) < target) __nanosleep(64);
    }
    __syncthreads();
}

__device__ __forceinline__ float eluf(float a) { return a > 0.f ? a : expm1f(a); }

__global__ void __launch_bounds__(NTHR, 1)
dgcnn_fused(const float* __restrict__ x,   const float* __restrict__ w,
            const int*   __restrict__ ei,  const float* __restrict__ ea,
            const float* __restrict__ g1b, const float* __restrict__ g2W,
            const float* __restrict__ g2b,
            const float* __restrict__ c1w, const float* __restrict__ c1b,
            const float* __restrict__ c2w, const float* __restrict__ c2b,
            const float* __restrict__ f1W, const float* __restrict__ f1b,
            const float* __restrict__ f2W, const float* __restrict__ f2b,
            const float* __restrict__ f3W, const float* __restrict__ f3b,
            float* __restrict__ out) {
    __shared__ float sred[32];
    __shared__ float s_xw[Nn], s_dinv[3 * Nn], s_h1f[3 * Nn];
    // tail buffers (only block 0 uses them, but cheap)
    __shared__ float s_h2a[3 * Nn];
    __shared__ float z0[3 * Nn], z1[3 * Nn];
    __shared__ float c1s[3 * 381], p1s[3 * 375], c2s[3 * 123];
    __shared__ float allx[363], f1s[32], f2s[6];

    const int t   = threadIdx.x;
    const int bid = blockIdx.x;
    const int lane = t & 31, warp = t >> 5;

    // ================= PHASE 1: degree scatter + big dot =================
    for (int e = bid * NTHR + t; e < Ee; e += GRID * NTHR) {
        int cc = ei[Ee + e];
#pragma unroll
        for (int ch = 0; ch < 3; ch++)
            atomicAdd(&g_deg[(ch * Nn + cc) * PADS], ea[e * 3 + ch]);
    }

    for (int tile = bid; tile < TILES; tile += GRID) {
        int r = tile >> 4, c = tile & 15;
        const float4* xp = (const float4*)x + ((size_t)r * Fdim + (size_t)c * CHF) / 4;
        const float4* wp = (const float4*)w + ((size_t)c * CHF) / 4;
        float acc = 0.f;
#pragma unroll
        for (int i = 0; i < CHF / 4 / NTHR; i++) {       // 4 float4 pairs / thread
            float4 a  = __ldcs(&xp[t + i * NTHR]);       // x: streamed, evict-first
            float4 bb = __ldg (&wp[t + i * NTHR]);       // w: L2-resident, reused 129x
            acc = fmaf(a.x, bb.x, acc);
            acc = fmaf(a.y, bb.y, acc);
            acc = fmaf(a.z, bb.z, acc);
            acc = fmaf(a.w, bb.w, acc);
        }
#pragma unroll
        for (int o = 16; o > 0; o >>= 1) acc += __shfl_down_sync(0xffffffffu, acc, o);
        if (lane == 0) sred[warp] = acc;
        __syncthreads();
        if (warp == 0) {
            float s = sred[lane];
#pragma unroll
            for (int o = 16; o > 0; o >>= 1) s += __shfl_down_sync(0xffffffffu, s, o);
            if (lane == 0) atomicAdd(&g_xwa[r * XPAD], s);
        }
        __syncthreads();
    }

    gridbar(0);

    // ================= PHASE 2: redundant dinv/xw -> smem, edge agg layer 1 =================
    for (int i = t; i < Nn; i += NTHR) s_xw[i] = __ldcg(&g_xwa[i * XPAD]);
    for (int i = t; i < 3 * Nn; i += NTHR) {
        float d = __ldcg(&g_deg[i * PADS]) + 1.0f;       // +1 self loop
        s_dinv[i] = (d > 0.f) ? rsqrtf(d) : 0.f;
    }
    __syncthreads();

    for (int e = bid * NTHR + t; e < Ee; e += GRID * NTHR) {
        int r = ei[e], c = ei[Ee + e];
#pragma unroll
        for (int ch = 0; ch < 3; ch++) {
            float ew  = ea[e * 3 + ch];
            float nrm = s_dinv[ch * Nn + r] * ew * s_dinv[ch * Nn + c];
            atomicAdd(&g_h1[(ch * Nn + c) * PADS], nrm * s_xw[r]);
        }
    }

    gridbar(1);

    // ================= PHASE 3: finalize h1 (redundant), edge agg layer 2 =================
    const float b1 = g1b[0], W2 = g2W[0];
    for (int i = t; i < 3 * Nn; i += NTHR) {
        float di = s_dinv[i];
        s_h1f[i] = __ldcg(&g_h1[i * PADS]) + di * di * s_xw[i % Nn] + b1;
    }
    __syncthreads();

    for (int e = bid * NTHR + t; e < Ee; e += GRID * NTHR) {
        int r = ei[e], c = ei[Ee + e];
#pragma unroll
        for (int ch = 0; ch < 3; ch++) {
            float ew  = ea[e * 3 + ch];
            float nrm = s_dinv[ch * Nn + r] * ew * s_dinv[ch * Nn + c];
            atomicAdd(&g_h2[(ch * Nn + c) * PADS], nrm * s_h1f[ch * Nn + r] * W2);
        }
    }

    gridbar(2);

    // ================= PHASE 4: cleanup (blocks 1..3) + tail (block 0) =================
    if (bid != 0) {
        if (bid == 1) for (int i = t; i < Nn; i += NTHR)     g_xwa[i * XPAD] = 0.f;
        if (bid == 2) for (int i = t; i < 3 * Nn; i += NTHR) g_deg[i * PADS] = 0.f;
        if (bid == 3) for (int i = t; i < 3 * Nn; i += NTHR) g_h1 [i * PADS] = 0.f;
        return;
    }

    // ---- finalize h2, zero g_h2 for next replay ----
    const float b2 = g2b[0];
    for (int i = t; i < 3 * Nn; i += NTHR) {
        float di = s_dinv[i];
        s_h2a[i] = __ldcg(&g_h2[i * PADS]) + di * di * s_h1f[i] * W2 + b2;
        g_h2[i * PADS] = 0.f;
    }
    __syncthreads();

    const int ch = t >> 8, tt = t & 255;   // 3 channels processed concurrently

    // ---- SortPool: stable descending by h2 (O(N^2) rank) ----
    if (ch < 3 && tt < Nn) {
        float key = s_h2a[ch * Nn + tt];
        float v1  = s_h1f[ch * Nn + tt];
        int rank = 0;
        for (int m = 0; m < Nn; m++) {
            float km = s_h2a[ch * Nn + m];
            rank += (km > key) || (km == key && m < tt);
        }
        z0[ch * Nn + rank] = v1;
        z1[ch * Nn + rank] = key;
    }
    __syncthreads();

    // ---- conv1: 2->3 ch, k=3 -> 127 ----
    if (ch < 3 && tt < 127) {
#pragma unroll
        for (int o = 0; o < 3; o++) {
            float a = c1b[o];
#pragma unroll
            for (int k = 0; k < 3; k++) {
                a = fmaf(c1w[o * 6 + k],     z0[ch * Nn + tt + k], a);
                a = fmaf(c1w[o * 6 + 3 + k], z1[ch * Nn + tt + k], a);
            }
            c1s[ch * 381 + o * 127 + tt] = a;
        }
    }
    __syncthreads();

    // ---- maxpool3 -> 125 ----
    if (ch < 3 && tt < 125) {
#pragma unroll
        for (int o = 0; o < 3; o++) {
            const float* p = &c1s[ch * 381 + o * 127 + tt];
            p1s[ch * 375 + o * 125 + tt] = fmaxf(p[0], fmaxf(p[1], p[2]));
        }
    }
    __syncthreads();

    // ---- conv2: 3->1, k=3 -> 123 ----
    if (ch < 3 && tt < 123) {
        float a = c2b[0];
#pragma unroll
        for (int in = 0; in < 3; in++)
#pragma unroll
            for (int k = 0; k < 3; k++)
                a = fmaf(c2w[in * 3 + k], p1s[ch * 375 + in * 125 + tt + k], a);
        c2s[ch * 123 + tt] = a;
    }
    __syncthreads();

    // ---- maxpool3 -> 121 ----
    if (ch < 3 && tt < 121) {
        const float* p = &c2s[ch * 123 + tt];
        allx[ch * 121 + tt] = fmaxf(p[0], fmaxf(p[1], p[2]));
    }
    __syncthreads();

    // ---- fc1: 363->32, elu ----
    if (t < 32) {
        float a = f1b[t];
        for (int i = 0; i < 363; i++) a = fmaf(allx[i], f1W[i * 32 + t], a);
        f1s[t] = eluf(a);
    }
    __syncthreads();
    // ---- fc2: 32->6, elu ----
    if (t < 6) {
        float a = f2b[t];
#pragma unroll
        for (int i = 0; i < 32; i++) a = fmaf(f1s[i], f2W[i * 6 + t], a);
        f2s[t] = eluf(a);
    }
    __syncthreads();
    // ---- fc3: 6->2 ----
    if (t < 2) {
        float a = f3b[t];
#pragma unroll
        for (int i = 0; i < 6; i++) a = fmaf(f2s[i], f3W[i * 2 + t], a);
        out[t] = a;
    }
}

// ---------------- launch ----------------
extern "C" void kernel_launch(void* const* d_in, const int* in_sizes, int n_in,
                              void* d_out, int out_size) {
    const float* x    = (const float*)d_in[0];
    const int*   ei   = (const int*)  d_in[1];
    const float* ea   = (const float*)d_in[2];
    const float* g1W  = (const float*)d_in[3];
    const float* g1b  = (const float*)d_in[4];
    const float* g2W  = (const float*)d_in[5];
    const float* g2b  = (const float*)d_in[6];
    const float* c1w  = (const float*)d_in[7];
    const float* c1b  = (const float*)d_in[8];
    const float* c2w  = (const float*)d_in[9];
    const float* c2b  = (const float*)d_in[10];
    const float* f1W  = (const float*)d_in[11];
    const float* f1b  = (const float*)d_in[12];
    const float* f2W  = (const float*)d_in[13];
    const float* f2b  = (const float*)d_in[14];
    const float* f3W  = (const float*)d_in[15];
    const float* f3b  = (const float*)d_in[16];
    float* out = (float*)d_out;

    dgcnn_fused<<<GRID, NTHR>>>(x, g1W, ei, ea, g1b, g2W, g2b,
                                c1w, c1b, c2w, c2b,
                                f1W, f1b, f2W, f2b, f3W, f3b, out);
}

// round 3
// speedup vs baseline: 1.2293x; 1.0316x over previous
#include <cuda_runtime.h>
#include <math.h>

// ---------------- problem constants ----------------
#define Nn      129
#define Fdim    262144
#define Ee      16384
#define GRID    148
#define NTHR    1024
#define NCOPY   8                      // replicated atomic accumulators
#define PADS    64                     // 256B stride between accumulator slots
#define NSLOT   (3 * Nn)               // 387 (ch,node) slots

// ---------------- device scratch ----------------
__device__ float    g_xw [Nn];                       // written by plain stores (no zeroing needed)
__device__ float    g_deg[NSLOT * PADS];             // degree accumulators (single copy)
__device__ float    g_h1 [NCOPY * NSLOT * PADS];     // layer-1 agg copies
__device__ float    g_h2 [NCOPY * NSLOT * PADS];     // layer-2 agg copies
__device__ unsigned g_bar[4];

// ---------------- grid barrier: monotonic counter, replay-safe ----------------
__device__ __forceinline__ void gridbar(int k) {
    __syncthreads();
    __threadfence();
    if (threadIdx.x == 0) {
        unsigned v = atomicAdd(&g_bar[k], 1u);
        unsigned target = (v / GRID) * GRID + GRID;
        while (atomicAdd(&g_bar[k], 0u) < target) __nanosleep(64);
    }
    __syncthreads();
}

__device__ __forceinline__ float eluf(float a) { return a > 0.f ? a : expm1f(a); }

__global__ void __launch_bounds__(NTHR, 1)
dgcnn_fused(const float* __restrict__ x,   const float* __restrict__ w,
            const int*   __restrict__ ei,  const float* __restrict__ ea,
            const float* __restrict__ g1b, const float* __restrict__ g2W,
            const float* __restrict__ g2b,
            const float* __restrict__ c1w, const float* __restrict__ c1b,
            const float* __restrict__ c2w, const float* __restrict__ c2b,
            const float* __restrict__ f1W, const float* __restrict__ f1b,
            const float* __restrict__ f2W, const float* __restrict__ f2b,
            const float* __restrict__ f3W, const float* __restrict__ f3b,
            float* __restrict__ out) {
    __shared__ float sred[32];
    __shared__ float s_xw[Nn], s_dinv[NSLOT], s_h1f[NSLOT];
    __shared__ float s_h2a[NSLOT];
    __shared__ float z0[NSLOT], z1[NSLOT];
    __shared__ float c1s[3 * 381], p1s[3 * 375], c2s[3 * 123];
    __shared__ float allx[363], f1s[32], f2s[6];

    const int t    = threadIdx.x;
    const int bid  = blockIdx.x;
    const int lane = t & 31, warp = t >> 5;

    // ================= PHASE 1 =================
    if (bid < Nn) {
        // --- block r == row r of the big dot. Warp-autonomous, no syncs in loop. ---
        const float4* xr = (const float4*)x + (size_t)bid * (Fdim / 4);
        const float4* wr = (const float4*)w;
        float4 acc = make_float4(0.f, 0.f, 0.f, 0.f);
        const int base = warp * 128 + lane;           // seg = warp (+32*i), 128 float4/seg
#pragma unroll 4
        for (int i = 0; i < 16; i++) {
            int o = base + i * 4096;                  // 32 segs * 128 f4 stride
            float4 a0 = __ldcs(xr + o);
            float4 a1 = __ldcs(xr + o + 32);
            float4 a2 = __ldcs(xr + o + 64);
            float4 a3 = __ldcs(xr + o + 96);
            float4 b0 = __ldcg(wr + o);
            float4 b1 = __ldcg(wr + o + 32);
            float4 b2 = __ldcg(wr + o + 64);
            float4 b3 = __ldcg(wr + o + 96);
            acc.x = fmaf(a0.x, b0.x, acc.x); acc.y = fmaf(a0.y, b0.y, acc.y);
            acc.z = fmaf(a0.z, b0.z, acc.z); acc.w = fmaf(a0.w, b0.w, acc.w);
            acc.x = fmaf(a1.x, b1.x, acc.x); acc.y = fmaf(a1.y, b1.y, acc.y);
            acc.z = fmaf(a1.z, b1.z, acc.z); acc.w = fmaf(a1.w, b1.w, acc.w);
            acc.x = fmaf(a2.x, b2.x, acc.x); acc.y = fmaf(a2.y, b2.y, acc.y);
            acc.z = fmaf(a2.z, b2.z, acc.z); acc.w = fmaf(a2.w, b2.w, acc.w);
            acc.x = fmaf(a3.x, b3.x, acc.x); acc.y = fmaf(a3.y, b3.y, acc.y);
            acc.z = fmaf(a3.z, b3.z, acc.z); acc.w = fmaf(a3.w, b3.w, acc.w);
        }
        float s = (acc.x + acc.y) + (acc.z + acc.w);
#pragma unroll
        for (int o = 16; o > 0; o >>= 1) s += __shfl_down_sync(0xffffffffu, s, o);
        if (lane == 0) sred[warp] = s;
        __syncthreads();
        if (warp == 0) {
            float v = sred[lane];
#pragma unroll
            for (int o = 16; o > 0; o >>= 1) v += __shfl_down_sync(0xffffffffu, v, o);
            if (lane == 0) g_xw[bid] = v;             // plain store, no atomic
        }
    } else {
        // --- blocks 129..147: degree scatter (hidden under the dot) ---
        int e = (bid - Nn) * NTHR + t;
        if (e < Ee) {
            int cc = ei[Ee + e];
#pragma unroll
            for (int ch = 0; ch < 3; ch++)
                atomicAdd(&g_deg[(ch * Nn + cc) * PADS], ea[e * 3 + ch]);
        }
    }

    gridbar(0);

    // ================= PHASE 2: dinv (redundant per block) + edge agg layer 1 =================
    for (int i = t; i < Nn; i += NTHR) s_xw[i] = __ldcg(&g_xw[i]);
    for (int i = t; i < NSLOT; i += NTHR) {
        float d = __ldcg(&g_deg[i * PADS]) + 1.0f;    // +1 self loop
        s_dinv[i] = (d > 0.f) ? rsqrtf(d) : 0.f;
    }
    __syncthreads();

    {
        int e = bid * NTHR + t;                       // blocks 0..15 carry the edges
        if (e < Ee) {
            int r = ei[e], c = ei[Ee + e];
            int cp = (bid & (NCOPY - 1)) * NSLOT;
#pragma unroll
            for (int ch = 0; ch < 3; ch++) {
                float ew  = ea[e * 3 + ch];
                float nrm = s_dinv[ch * Nn + r] * ew * s_dinv[ch * Nn + c];
                atomicAdd(&g_h1[(cp + ch * Nn + c) * PADS], nrm * s_xw[r]);
            }
        }
    }

    gridbar(1);

    // ================= PHASE 3: finalize h1 (redundant), edge agg layer 2 =================
    const float b1 = g1b[0], W2 = g2W[0];
    for (int i = t; i < NSLOT; i += NTHR) {
        float acc1 = 0.f;
#pragma unroll
        for (int c = 0; c < NCOPY; c++) acc1 += __ldcg(&g_h1[(c * NSLOT + i) * PADS]);
        float di = s_dinv[i];
        s_h1f[i] = acc1 + di * di * s_xw[i % Nn] + b1;
    }
    __syncthreads();

    {
        int e = bid * NTHR + t;
        if (e < Ee) {
            int r = ei[e], c = ei[Ee + e];
            int cp = (bid & (NCOPY - 1)) * NSLOT;
#pragma unroll
            for (int ch = 0; ch < 3; ch++) {
                float ew  = ea[e * 3 + ch];
                float nrm = s_dinv[ch * Nn + r] * ew * s_dinv[ch * Nn + c];
                atomicAdd(&g_h2[(cp + ch * Nn + c) * PADS], nrm * s_h1f[ch * Nn + r] * W2);
            }
        }
    }
    // g_deg no longer needed after this point: block 140 zeros it for next replay
    if (bid == 140)
        for (int i = t; i < NSLOT; i += NTHR) g_deg[i * PADS] = 0.f;

    gridbar(2);

    // ================= PHASE 4: cleanup + tail =================
    if (bid != 0) {
        if (bid >= 1 && bid <= NCOPY) {               // blocks 1..8 zero the h1 copies
            int c = bid - 1;
            for (int i = t; i < NSLOT; i += NTHR) g_h1[(c * NSLOT + i) * PADS] = 0.f;
        }
        return;
    }

    // ---- block 0: finalize h2, zero its copies ----
    const float b2 = g2b[0];
    for (int i = t; i < NSLOT; i += NTHR) {
        float acc2 = 0.f;
#pragma unroll
        for (int c = 0; c < NCOPY; c++) {
            acc2 += __ldcg(&g_h2[(c * NSLOT + i) * PADS]);
            g_h2[(c * NSLOT + i) * PADS] = 0.f;
        }
        float di = s_dinv[i];
        s_h2a[i] = acc2 + di * di * s_h1f[i] * W2 + b2;
    }
    __syncthreads();

    const int ch = t >> 8, tt = t & 255;              // 3 channels concurrent

    // ---- SortPool: stable descending by h2 ----
    if (ch < 3 && tt < Nn) {
        float key = s_h2a[ch * Nn + tt];
        float v1  = s_h1f[ch * Nn + tt];
        int rank = 0;
        for (int m = 0; m < Nn; m++) {
            float km = s_h2a[ch * Nn + m];
            rank += (km > key) || (km == key && m < tt);
        }
        z0[ch * Nn + rank] = v1;
        z1[ch * Nn + rank] = key;
    }
    __syncthreads();

    // ---- conv1: 2->3 ch, k=3 -> 127 ----
    if (ch < 3 && tt < 127) {
#pragma unroll
        for (int o = 0; o < 3; o++) {
            float a = c1b[o];
#pragma unroll
            for (int k = 0; k < 3; k++) {
                a = fmaf(c1w[o * 6 + k],     z0[ch * Nn + tt + k], a);
                a = fmaf(c1w[o * 6 + 3 + k], z1[ch * Nn + tt + k], a);
            }
            c1s[ch * 381 + o * 127 + tt] = a;
        }
    }
    __syncthreads();

    // ---- maxpool3 -> 125 ----
    if (ch < 3 && tt < 125) {
#pragma unroll
        for (int o = 0; o < 3; o++) {
            const float* p = &c1s[ch * 381 + o * 127 + tt];
            p1s[ch * 375 + o * 125 + tt] = fmaxf(p[0], fmaxf(p[1], p[2]));
        }
    }
    __syncthreads();

    // ---- conv2: 3->1, k=3 -> 123 ----
    if (ch < 3 && tt < 123) {
        float a = c2b[0];
#pragma unroll
        for (int in = 0; in < 3; in++)
#pragma unroll
            for (int k = 0; k < 3; k++)
                a = fmaf(c2w[in * 3 + k], p1s[ch * 375 + in * 125 + tt + k], a);
        c2s[ch * 123 + tt] = a;
    }
    __syncthreads();

    // ---- maxpool3 -> 121 ----
    if (ch < 3 && tt < 121) {
        const float* p = &c2s[ch * 123 + tt];
        allx[ch * 121 + tt] = fmaxf(p[0], fmaxf(p[1], p[2]));
    }
    __syncthreads();

    // ---- fc1: 363->32, elu — warp per output ----
    {
        float a = 0.f;
        for (int i = lane; i < 363; i += 32) a = fmaf(allx[i], f1W[i * 32 + warp], a);
#pragma unroll
        for (int o = 16; o > 0; o >>= 1) a += __shfl_down_sync(0xffffffffu, a, o);
        if (lane == 0) f1s[warp] = eluf(a + f1b[warp]);
    }
    __syncthreads();
    // ---- fc2: 32->6, elu ----
    if (t < 6) {
        float a = f2b[t];
#pragma unroll
        for (int i = 0; i < 32; i++) a = fmaf(f1s[i], f2W[i * 6 + t], a);
        f2s[t] = eluf(a);
    }
    __syncthreads();
    // ---- fc3: 6->2 ----
    if (t < 2) {
        float a = f3b[t];
#pragma unroll
        for (int i = 0; i < 6; i++) a = fmaf(f2s[i], f3W[i * 2 + t], a);
        out[t] = a;
    }
}

// ---------------- launch ----------------
extern "C" void kernel_launch(void* const* d_in, const int* in_sizes, int n_in,
                              void* d_out, int out_size) {
    const float* x    = (const float*)d_in[0];
    const int*   ei   = (const int*)  d_in[1];
    const float* ea   = (const float*)d_in[2];
    const float* g1W  = (const float*)d_in[3];
    const float* g1b  = (const float*)d_in[4];
    const float* g2W  = (const float*)d_in[5];
    const float* g2b  = (const float*)d_in[6];
    const float* c1w  = (const float*)d_in[7];
    const float* c1b  = (const float*)d_in[8];
    const float* c2w  = (const float*)d_in[9];
    const float* c2b  = (const float*)d_in[10];
    const float* f1W  = (const float*)d_in[11];
    const float* f1b  = (const float*)d_in[12];
    const float* f2W  = (const float*)d_in[13];
    const float* f2b  = (const float*)d_in[14];
    const float* f3W  = (const float*)d_in[15];
    const float* f3b  = (const float*)d_in[16];
    float* out = (float*)d_out;

    dgcnn_fused<<<GRID, NTHR>>>(x, g1W, ei, ea, g1b, g2W, g2b,
                                c1w, c1b, c2w, c2b,
                                f1W, f1b, f2W, f2b, f3W, f3b, out);
}

// round 4
// speedup vs baseline: 1.2547x; 1.0207x over previous
#include <cuda_runtime.h>
#include <math.h>

// ---------------- problem constants ----------------
#define Nn      129
#define Fdim    262144
#define Ee      16384
#define GRID    148
#define NTHR    512
#define NCOPY   8                      // replicated atomic accumulators
#define PADS    64                     // 256B stride between accumulator slots
#define NSLOT   (3 * Nn)               // 387 (ch,node) slots

// ---------------- device scratch ----------------
__device__ float    g_xw [Nn];
__device__ float    g_deg[NSLOT * PADS];
__device__ float    g_h1 [NCOPY * NSLOT * PADS];
__device__ float    g_h2 [NCOPY * NSLOT * PADS];
__device__ unsigned g_bar[4];

// ---------------- grid barrier: monotonic counter, replay-safe ----------------
__device__ __forceinline__ void gridbar(int k) {
    __syncthreads();
    __threadfence();
    if (threadIdx.x == 0) {
        unsigned v = atomicAdd(&g_bar[k], 1u);
        unsigned target = (v / GRID) * GRID + GRID;
        while (atomicAdd(&g_bar[k], 0u) < target) __nanosleep(64);
    }
    __syncthreads();
}

__device__ __forceinline__ float eluf(float a) { return a > 0.f ? a : expm1f(a); }

__global__ void __launch_bounds__(NTHR, 1)
dgcnn_fused(const float* __restrict__ x,   const float* __restrict__ w,
            const int*   __restrict__ ei,  const float* __restrict__ ea,
            const float* __restrict__ g1b, const float* __restrict__ g2W,
            const float* __restrict__ g2b,
            const float* __restrict__ c1w, const float* __restrict__ c1b,
            const float* __restrict__ c2w, const float* __restrict__ c2b,
            const float* __restrict__ f1W, const float* __restrict__ f1b,
            const float* __restrict__ f2W, const float* __restrict__ f2b,
            const float* __restrict__ f3W, const float* __restrict__ f3b,
            float* __restrict__ out) {
    __shared__ float sred[16];
    __shared__ float s_xw[Nn], s_dinv[NSLOT], s_h1f[NSLOT];
    __shared__ float s_h2a[NSLOT];
    __shared__ float z0[Nn], z1[Nn];
    __shared__ float c1s[3 * 127], p1s[3 * 125], c2s[123];
    __shared__ float allx[363], f1s[32], f2s[6];

    const int t    = threadIdx.x;
    const int bid  = blockIdx.x;
    const int lane = t & 31, warp = t >> 5;

    // ================= PHASE 1 =================
    if (bid < Nn) {
        // block r == row r. 16 warps. 8 x-loads + 8 w-loads batched per iter (MLP=16).
        const float4* __restrict__ xr = (const float4*)x + (size_t)bid * (Fdim / 4);
        const float4* __restrict__ wr = (const float4*)w;
        const int base = warp * 256 + lane;
        float4 acc0 = make_float4(0.f, 0.f, 0.f, 0.f);
        float4 acc1 = acc0, acc2 = acc0, acc3 = acc0;
#pragma unroll 1
        for (int i = 0; i < 16; i++) {
            const int o = base + i * 4096;
            float4 a0 = __ldcs(xr + o);
            float4 a1 = __ldcs(xr + o + 32);
            float4 a2 = __ldcs(xr + o + 64);
            float4 a3 = __ldcs(xr + o + 96);
            float4 a4 = __ldcs(xr + o + 128);
            float4 a5 = __ldcs(xr + o + 160);
            float4 a6 = __ldcs(xr + o + 192);
            float4 a7 = __ldcs(xr + o + 224);
            float4 b0 = __ldcg(wr + o);
            float4 b1 = __ldcg(wr + o + 32);
            float4 b2 = __ldcg(wr + o + 64);
            float4 b3 = __ldcg(wr + o + 96);
            float4 b4 = __ldcg(wr + o + 128);
            float4 b5 = __ldcg(wr + o + 160);
            float4 b6 = __ldcg(wr + o + 192);
            float4 b7 = __ldcg(wr + o + 224);
            acc0.x = fmaf(a0.x, b0.x, acc0.x); acc0.y = fmaf(a0.y, b0.y, acc0.y);
            acc0.z = fmaf(a0.z, b0.z, acc0.z); acc0.w = fmaf(a0.w, b0.w, acc0.w);
            acc1.x = fmaf(a1.x, b1.x, acc1.x); acc1.y = fmaf(a1.y, b1.y, acc1.y);
            acc1.z = fmaf(a1.z, b1.z, acc1.z); acc1.w = fmaf(a1.w, b1.w, acc1.w);
            acc2.x = fmaf(a2.x, b2.x, acc2.x); acc2.y = fmaf(a2.y, b2.y, acc2.y);
            acc2.z = fmaf(a2.z, b2.z, acc2.z); acc2.w = fmaf(a2.w, b2.w, acc2.w);
            acc3.x = fmaf(a3.x, b3.x, acc3.x); acc3.y = fmaf(a3.y, b3.y, acc3.y);
            acc3.z = fmaf(a3.z, b3.z, acc3.z); acc3.w = fmaf(a3.w, b3.w, acc3.w);
            acc0.x = fmaf(a4.x, b4.x, acc0.x); acc0.y = fmaf(a4.y, b4.y, acc0.y);
            acc0.z = fmaf(a4.z, b4.z, acc0.z); acc0.w = fmaf(a4.w, b4.w, acc0.w);
            acc1.x = fmaf(a5.x, b5.x, acc1.x); acc1.y = fmaf(a5.y, b5.y, acc1.y);
            acc1.z = fmaf(a5.z, b5.z, acc1.z); acc1.w = fmaf(a5.w, b5.w, acc1.w);
            acc2.x = fmaf(a6.x, b6.x, acc2.x); acc2.y = fmaf(a6.y, b6.y, acc2.y);
            acc2.z = fmaf(a6.z, b6.z, acc2.z); acc2.w = fmaf(a6.w, b6.w, acc2.w);
            acc3.x = fmaf(a7.x, b7.x, acc3.x); acc3.y = fmaf(a7.y, b7.y, acc3.y);
            acc3.z = fmaf(a7.z, b7.z, acc3.z); acc3.w = fmaf(a7.w, b7.w, acc3.w);
        }
        acc0.x = (acc0.x + acc0.y) + (acc0.z + acc0.w);
        acc1.x = (acc1.x + acc1.y) + (acc1.z + acc1.w);
        acc2.x = (acc2.x + acc2.y) + (acc2.z + acc2.w);
        acc3.x = (acc3.x + acc3.y) + (acc3.z + acc3.w);
        float s = (acc0.x + acc1.x) + (acc2.x + acc3.x);
#pragma unroll
        for (int o = 16; o > 0; o >>= 1) s += __shfl_down_sync(0xffffffffu, s, o);
        if (lane == 0) sred[warp] = s;
        __syncthreads();
        if (t == 0) {
            float v = 0.f;
#pragma unroll
            for (int i = 0; i < 16; i++) v += sred[i];
            g_xw[bid] = v;
        }
    } else {
        // blocks 129..147: degree scatter (hidden under the dot)
        for (int e = (bid - Nn) * NTHR + t; e < Ee; e += (GRID - Nn) * NTHR) {
            int cc = ei[Ee + e];
#pragma unroll
            for (int ch = 0; ch < 3; ch++)
                atomicAdd(&g_deg[(ch * Nn + cc) * PADS], ea[e * 3 + ch]);
        }
    }

    gridbar(0);

    // ================= PHASE 2: dinv (redundant) + edge agg layer 1 =================
    for (int i = t; i < Nn; i += NTHR) s_xw[i] = __ldcg(&g_xw[i]);
    for (int i = t; i < NSLOT; i += NTHR) {
        float d = __ldcg(&g_deg[i * PADS]) + 1.0f;    // +1 self loop
        s_dinv[i] = (d > 0.f) ? rsqrtf(d) : 0.f;
    }
    __syncthreads();

    {
        int e = bid * NTHR + t;                       // blocks 0..31 carry edges
        if (e < Ee) {
            int r = ei[e], c = ei[Ee + e];
            int cp = (bid & (NCOPY - 1)) * NSLOT;
#pragma unroll
            for (int ch = 0; ch < 3; ch++) {
                float ew  = ea[e * 3 + ch];
                float nrm = s_dinv[ch * Nn + r] * ew * s_dinv[ch * Nn + c];
                atomicAdd(&g_h1[(cp + ch * Nn + c) * PADS], nrm * s_xw[r]);
            }
        }
    }

    gridbar(1);

    // ================= PHASE 3: finalize h1 (redundant), edge agg layer 2 =================
    const float b1 = g1b[0], W2 = g2W[0];
    for (int i = t; i < NSLOT; i += NTHR) {
        float acc1 = 0.f;
#pragma unroll
        for (int c = 0; c < NCOPY; c++) acc1 += __ldcg(&g_h1[(c * NSLOT + i) * PADS]);
        float di = s_dinv[i];
        s_h1f[i] = acc1 + di * di * s_xw[i % Nn] + b1;
    }
    __syncthreads();

    {
        int e = bid * NTHR + t;
        if (e < Ee) {
            int r = ei[e], c = ei[Ee + e];
            int cp = (bid & (NCOPY - 1)) * NSLOT;
#pragma unroll
            for (int ch = 0; ch < 3; ch++) {
                float ew  = ea[e * 3 + ch];
                float nrm = s_dinv[ch * Nn + r] * ew * s_dinv[ch * Nn + c];
                atomicAdd(&g_h2[(cp + ch * Nn + c) * PADS], nrm * s_h1f[ch * Nn + r] * W2);
            }
        }
    }
    if (bid == 140)                                   // g_deg dead after phase 2 reads
        for (int i = t; i < NSLOT; i += NTHR) g_deg[i * PADS] = 0.f;

    gridbar(2);

    // ================= PHASE 4: cleanup + tail =================
    if (bid != 0) {
        if (bid >= 1 && bid <= NCOPY) {               // blocks 1..8 zero h1 copies
            int c = bid - 1;
            for (int i = t; i < NSLOT; i += NTHR) g_h1[(c * NSLOT + i) * PADS] = 0.f;
        }
        return;
    }

    // ---- block 0: finalize h2, zero its copies ----
    const float b2 = g2b[0];
    for (int i = t; i < NSLOT; i += NTHR) {
        float acc2 = 0.f;
#pragma unroll
        for (int c = 0; c < NCOPY; c++) {
            acc2 += __ldcg(&g_h2[(c * NSLOT + i) * PADS]);
            g_h2[(c * NSLOT + i) * PADS] = 0.f;
        }
        float di = s_dinv[i];
        s_h2a[i] = acc2 + di * di * s_h1f[i] * W2 + b2;
    }
    __syncthreads();

    for (int ch = 0; ch < 3; ch++) {
        // ---- SortPool: stable descending by h2 ----
        if (t < Nn) {
            float key = s_h2a[ch * Nn + t];
            float v1  = s_h1f[ch * Nn + t];
            int rank = 0;
            for (int m = 0; m < Nn; m++) {
                float km = s_h2a[ch * Nn + m];
                rank += (km > key) || (km == key && m < t);
            }
            z0[rank] = v1;
            z1[rank] = key;
        }
        __syncthreads();

        // ---- conv1: 2->3 ch, k=3 -> 127 ----
        if (t < 127) {
#pragma unroll
            for (int o = 0; o < 3; o++) {
                float a = c1b[o];
#pragma unroll
                for (int k = 0; k < 3; k++) {
                    a = fmaf(c1w[o * 6 + k],     z0[t + k], a);
                    a = fmaf(c1w[o * 6 + 3 + k], z1[t + k], a);
                }
                c1s[o * 127 + t] = a;
            }
        }
        __syncthreads();

        // ---- maxpool3 -> 125 ----
        if (t < 125) {
#pragma unroll
            for (int o = 0; o < 3; o++) {
                const float* p = &c1s[o * 127 + t];
                p1s[o * 125 + t] = fmaxf(p[0], fmaxf(p[1], p[2]));
            }
        }
        __syncthreads();

        // ---- conv2: 3->1, k=3 -> 123 ----
        if (t < 123) {
            float a = c2b[0];
#pragma unroll
            for (int in = 0; in < 3; in++)
#pragma unroll
                for (int k = 0; k < 3; k++)
                    a = fmaf(c2w[in * 3 + k], p1s[in * 125 + t + k], a);
            c2s[t] = a;
        }
        __syncthreads();

        // ---- maxpool3 -> 121 ----
        if (t < 121) {
            const float* p = &c2s[t];
            allx[ch * 121 + t] = fmaxf(p[0], fmaxf(p[1], p[2]));
        }
        __syncthreads();
    }

    // ---- fc1: 363->32, elu — 2 outputs per warp ----
    for (int o = warp; o < 32; o += 16) {
        float a = 0.f;
        for (int i = lane; i < 363; i += 32) a = fmaf(allx[i], f1W[i * 32 + o], a);
#pragma unroll
        for (int s = 16; s > 0; s >>= 1) a += __shfl_down_sync(0xffffffffu, a, s);
        if (lane == 0) f1s[o] = eluf(a + f1b[o]);
    }
    __syncthreads();
    // ---- fc2: 32->6, elu ----
    if (t < 6) {
        float a = f2b[t];
#pragma unroll
        for (int i = 0; i < 32; i++) a = fmaf(f1s[i], f2W[i * 6 + t], a);
        f2s[t] = eluf(a);
    }
    __syncthreads();
    // ---- fc3: 6->2 ----
    if (t < 2) {
        float a = f3b[t];
#pragma unroll
        for (int i = 0; i < 6; i++) a = fmaf(f2s[i], f3W[i * 2 + t], a);
        out[t] = a;
    }
}

// ---------------- launch ----------------
extern "C" void kernel_launch(void* const* d_in, const int* in_sizes, int n_in,
                              void* d_out, int out_size) {
    const float* x    = (const float*)d_in[0];
    const int*   ei   = (const int*)  d_in[1];
    const float* ea   = (const float*)d_in[2];
    const float* g1W  = (const float*)d_in[3];
    const float* g1b  = (const float*)d_in[4];
    const float* g2W  = (const float*)d_in[5];
    const float* g2b  = (const float*)d_in[6];
    const float* c1w  = (const float*)d_in[7];
    const float* c1b  = (const float*)d_in[8];
    const float* c2w  = (const float*)d_in[9];
    const float* c2b  = (const float*)d_in[10];
    const float* f1W  = (const float*)d_in[11];
    const float* f1b  = (const float*)d_in[12];
    const float* f2W  = (const float*)d_in[13];
    const float* f2b  = (const float*)d_in[14];
    const float* f3W  = (const float*)d_in[15];
    const float* f3b  = (const float*)d_in[16];
    float* out = (float*)d_out;

    dgcnn_fused<<<GRID, NTHR>>>(x, g1W, ei, ea, g1b, g2W, g2b,
                                c1w, c1b, c2w, c2b,
                                f1W, f1b, f2W, f2b, f3W, f3b, out);
}